// round 1
// baseline (speedup 1.0000x reference)
#include <cuda_runtime.h>
#include <math.h>

#define HIDDEN 2048
#define NUM_HEADS 16
#define HEAD_DIM 128
#define BLOCK_SIZE 64
#define NUM_SEQS 64
#define MAX_SEQ_LEN 2048
#define MAX_BLOCKS 32
#define NUM_BLOCKS_KV 2048
#define SCALE 0.08838834764831843f   // 1/sqrt(128)

// Scratch (device globals; no allocation allowed)
__device__ float g_q[NUM_SEQS * HIDDEN];       // Q projection result
__device__ float g_attn[NUM_SEQS * HIDDEN];    // attention output
__device__ float g_part[4 * NUM_SEQS * HIDDEN]; // split-K partials

// ---------------------------------------------------------------------------
// Split-K GEMM: C_partial[ks] = A[64 x K] @ B[K x N (ldb)]  (n-tile 64 wide)
// block: 256 threads, tile 64x64, BK=16, thread tile 4x4, split-K over grid.y
// ---------------------------------------------------------------------------
__global__ __launch_bounds__(256) void gemm_splitk(
    const float* __restrict__ A, const float* __restrict__ B,
    float* __restrict__ P, int K, int ldb, int N)
{
    const int KSPLIT = 4;
    const int KS = K / KSPLIT;
    const int k_base = blockIdx.y * KS;
    const int n0 = blockIdx.x * 64;

    __shared__ float As[64][16];
    __shared__ float Bs[16][64];

    const int tid = threadIdx.x;
    const int tx = tid & 15;   // N dir (x4)
    const int ty = tid >> 4;   // M dir (x4)

    float acc[4][4];
#pragma unroll
    for (int i = 0; i < 4; i++)
#pragma unroll
        for (int j = 0; j < 4; j++) acc[i][j] = 0.f;

    float ra[4], rb[4];

    // prefetch first tile to registers
#pragma unroll
    for (int i = 0; i < 4; i++) {
        int e = i * 256 + tid;
        ra[i] = A[(e >> 4) * K + k_base + (e & 15)];
    }
#pragma unroll
    for (int i = 0; i < 4; i++) {
        int e = i * 256 + tid;
        rb[i] = B[(size_t)(k_base + (e >> 6)) * ldb + n0 + (e & 63)];
    }

    for (int k0 = k_base; k0 < k_base + KS; k0 += 16) {
        // regs -> smem
#pragma unroll
        for (int i = 0; i < 4; i++) {
            int e = i * 256 + tid;
            As[e >> 4][e & 15] = ra[i];
        }
#pragma unroll
        for (int i = 0; i < 4; i++) {
            int e = i * 256 + tid;
            Bs[e >> 6][e & 63] = rb[i];
        }
        __syncthreads();

        // prefetch next tile (overlaps compute)
        if (k0 + 16 < k_base + KS) {
            int kn = k0 + 16;
#pragma unroll
            for (int i = 0; i < 4; i++) {
                int e = i * 256 + tid;
                ra[i] = A[(e >> 4) * K + kn + (e & 15)];
            }
#pragma unroll
            for (int i = 0; i < 4; i++) {
                int e = i * 256 + tid;
                rb[i] = B[(size_t)(kn + (e >> 6)) * ldb + n0 + (e & 63)];
            }
        }

#pragma unroll
        for (int kk = 0; kk < 16; kk++) {
            float4 b4 = *(const float4*)&Bs[kk][tx * 4];
            float a[4];
#pragma unroll
            for (int i = 0; i < 4; i++) a[i] = As[ty * 4 + i][kk];
#pragma unroll
            for (int i = 0; i < 4; i++) {
                acc[i][0] += a[i] * b4.x;
                acc[i][1] += a[i] * b4.y;
                acc[i][2] += a[i] * b4.z;
                acc[i][3] += a[i] * b4.w;
            }
        }
        __syncthreads();
    }

    float* Pp = P + (size_t)blockIdx.y * 64 * N;
#pragma unroll
    for (int i = 0; i < 4; i++)
#pragma unroll
        for (int j = 0; j < 4; j++)
            Pp[(ty * 4 + i) * N + n0 + tx * 4 + j] = acc[i][j];
}

// reduce 4 split-K partials + bias
__global__ void reduce4(const float* __restrict__ P, const float* __restrict__ bias,
                        float* __restrict__ C, int N, int total)
{
    int i = blockIdx.x * blockDim.x + threadIdx.x;
    if (i < total) {
        float v = P[i] + P[total + i] + P[2 * total + i] + P[3 * total + i];
        C[i] = v + bias[i % N];
    }
}

// ---------------------------------------------------------------------------
// Paged attention decode: one block per (seq, head), 128 threads (4 warps)
// ---------------------------------------------------------------------------
__global__ __launch_bounds__(128) void attn_kernel(
    const float* __restrict__ kv_cache,      // [2, NB, bs, h, d]
    const int* __restrict__ block_tables,    // [S, MAX_BLOCKS]
    const int* __restrict__ seq_lens,        // [S]
    const float* __restrict__ qbuf,          // [S, HIDDEN]
    float* __restrict__ out)                 // [S, HIDDEN]
{
    const int s = blockIdx.x;
    const int h = blockIdx.y;
    const int L = seq_lens[s];
    const int tid = threadIdx.x;
    const int warp = tid >> 5;
    const int lane = tid & 31;

    __shared__ float q[HEAD_DIM];
    __shared__ float scores[MAX_SEQ_LEN];
    __shared__ float red[4];

    q[tid] = qbuf[s * HIDDEN + h * HEAD_DIM + tid];
    __syncthreads();

    const float4 qv = *(const float4*)&q[lane * 4];
    const float* kc = kv_cache;
    const float* vc = kv_cache + (size_t)NUM_BLOCKS_KV * BLOCK_SIZE * NUM_HEADS * HEAD_DIM;
    const int* bt = block_tables + s * MAX_BLOCKS;

    // Pass 1: scores = scale * (q . K[t]); warp per token, strided by 4
    float lmax = -INFINITY;
#pragma unroll 4
    for (int t = warp; t < L; t += 4) {
        int blk = bt[t >> 6];
        const float* kr = kc + (((size_t)blk * BLOCK_SIZE + (t & 63)) * NUM_HEADS + h) * HEAD_DIM;
        float4 k4 = *(const float4*)(kr + lane * 4);
        float d = qv.x * k4.x + qv.y * k4.y + qv.z * k4.z + qv.w * k4.w;
#pragma unroll
        for (int o = 16; o; o >>= 1) d += __shfl_xor_sync(0xffffffffu, d, o);
        d *= SCALE;
        if (lane == 0) scores[t] = d;
        lmax = fmaxf(lmax, d);
    }
    if (lane == 0) red[warp] = lmax;
    __syncthreads();
    float gmax = fmaxf(fmaxf(red[0], red[1]), fmaxf(red[2], red[3]));
    __syncthreads();

    // exp + sum
    float lsum = 0.f;
    for (int t = tid; t < L; t += 128) {
        float e = __expf(scores[t] - gmax);
        scores[t] = e;
        lsum += e;
    }
#pragma unroll
    for (int o = 16; o; o >>= 1) lsum += __shfl_xor_sync(0xffffffffu, lsum, o);
    if (lane == 0) red[warp] = lsum;
    __syncthreads();
    float inv = 1.f / (red[0] + red[1] + red[2] + red[3]);
    __syncthreads();

    // Pass 2: out = sum_t w[t] * V[t]; warp per token stride 4, lane owns 4 dims
    float4 acc = make_float4(0.f, 0.f, 0.f, 0.f);
#pragma unroll 4
    for (int t = warp; t < L; t += 4) {
        int blk = bt[t >> 6];
        const float* vr = vc + (((size_t)blk * BLOCK_SIZE + (t & 63)) * NUM_HEADS + h) * HEAD_DIM;
        float4 v4 = *(const float4*)(vr + lane * 4);
        float w = scores[t];
        acc.x += w * v4.x;
        acc.y += w * v4.y;
        acc.z += w * v4.z;
        acc.w += w * v4.w;
    }
    __syncthreads();  // all warps done reading scores
    ((float4*)scores)[warp * 32 + lane] = acc;   // [warp][128 dims]
    __syncthreads();

    // final cross-warp reduce: thread tid owns dim tid
    float tot = scores[0 * 128 + tid] + scores[1 * 128 + tid] +
                scores[2 * 128 + tid] + scores[3 * 128 + tid];
    out[s * HIDDEN + h * HEAD_DIM + tid] = tot * inv;
}

// ---------------------------------------------------------------------------
extern "C" void kernel_launch(void* const* d_in, const int* in_sizes, int n_in,
                              void* d_out, int out_size)
{
    const float* hidden  = (const float*)d_in[0];
    const float* kvcache = (const float*)d_in[1];
    const float* W_attn  = (const float*)d_in[2];
    const float* b_attn  = (const float*)d_in[3];
    const float* W_proj  = (const float*)d_in[4];
    const float* b_proj  = (const float*)d_in[5];
    const int*   btab    = (const int*)d_in[6];
    const int*   slens   = (const int*)d_in[7];
    float* out = (float*)d_out;

    float *gq, *gattn, *gpart;
    cudaGetSymbolAddress((void**)&gq, g_q);
    cudaGetSymbolAddress((void**)&gattn, g_attn);
    cudaGetSymbolAddress((void**)&gpart, g_part);

    const int total = NUM_SEQS * HIDDEN;  // 131072

    // 1) Q projection only (first HIDDEN columns of W_attn), split-K=4
    gemm_splitk<<<dim3(HIDDEN / 64, 4), 256>>>(hidden, W_attn, gpart, HIDDEN, 3 * HIDDEN, HIDDEN);
    reduce4<<<(total + 255) / 256, 256>>>(gpart, b_attn, gq, HIDDEN, total);

    // 2) paged attention
    attn_kernel<<<dim3(NUM_SEQS, NUM_HEADS), 128>>>(kvcache, btab, slens, gq, gattn);

    // 3) output projection, split-K=4
    gemm_splitk<<<dim3(HIDDEN / 64, 4), 256>>>(gattn, W_proj, gpart, HIDDEN, HIDDEN, HIDDEN);
    reduce4<<<(total + 255) / 256, 256>>>(gpart, b_proj, out, HIDDEN, total);
}

// round 2
// speedup vs baseline: 2.1691x; 2.1691x over previous
#include <cuda_runtime.h>
#include <math.h>

#define HIDDEN 2048
#define NUM_HEADS 16
#define HEAD_DIM 128
#define BLOCK_SIZE 64
#define NUM_SEQS 64
#define MAX_SEQ_LEN 2048
#define MAX_BLOCKS 32
#define NUM_BLOCKS_KV 2048
#define SCALE 0.08838834764831843f   // 1/sqrt(128)

#define KSPLIT 16
#define PART 4
#define PART_LEN 512   // MAX_SEQ_LEN / PART

// Scratch (device globals; no allocation allowed)
__device__ float g_q[NUM_SEQS * HIDDEN];                   // Q projection result
__device__ float g_attn[NUM_SEQS * HIDDEN];                // attention output
__device__ float g_part[KSPLIT * NUM_SEQS * HIDDEN];       // split-K partials (8MB)
__device__ float g_pacc[NUM_SEQS * NUM_HEADS * PART * HEAD_DIM]; // attn partial accum
__device__ float2 g_pml[NUM_SEQS * NUM_HEADS * PART];      // attn partial (m, l)

// ---------------------------------------------------------------------------
// Split-K GEMM: P[ks] = A[64 x K-slice] @ B[K x N (ldb)]  (n-tile 64 wide)
// block: 256 threads, tile 64x64, BK=16, thread tile 4x4, split-K=16 over grid.y
// ---------------------------------------------------------------------------
__global__ __launch_bounds__(256) void gemm_splitk(
    const float* __restrict__ A, const float* __restrict__ B,
    float* __restrict__ P, int K, int ldb, int N)
{
    const int KS = K / KSPLIT;              // 128
    const int k_base = blockIdx.y * KS;
    const int n0 = blockIdx.x * 64;

    __shared__ float As[64][17];            // padded: conflict-free reads
    __shared__ float Bs[16][64];

    const int tid = threadIdx.x;
    const int tx = tid & 15;   // N dir (x4)
    const int ty = tid >> 4;   // M dir (x4)

    float acc[4][4];
#pragma unroll
    for (int i = 0; i < 4; i++)
#pragma unroll
        for (int j = 0; j < 4; j++) acc[i][j] = 0.f;

    float ra[4], rb[4];

#pragma unroll
    for (int i = 0; i < 4; i++) {
        int e = i * 256 + tid;
        ra[i] = A[(e >> 4) * K + k_base + (e & 15)];
    }
#pragma unroll
    for (int i = 0; i < 4; i++) {
        int e = i * 256 + tid;
        rb[i] = B[(size_t)(k_base + (e >> 6)) * ldb + n0 + (e & 63)];
    }

    for (int k0 = k_base; k0 < k_base + KS; k0 += 16) {
#pragma unroll
        for (int i = 0; i < 4; i++) {
            int e = i * 256 + tid;
            As[e >> 4][e & 15] = ra[i];
        }
#pragma unroll
        for (int i = 0; i < 4; i++) {
            int e = i * 256 + tid;
            Bs[e >> 6][e & 63] = rb[i];
        }
        __syncthreads();

        if (k0 + 16 < k_base + KS) {
            int kn = k0 + 16;
#pragma unroll
            for (int i = 0; i < 4; i++) {
                int e = i * 256 + tid;
                ra[i] = A[(e >> 4) * K + kn + (e & 15)];
            }
#pragma unroll
            for (int i = 0; i < 4; i++) {
                int e = i * 256 + tid;
                rb[i] = B[(size_t)(kn + (e >> 6)) * ldb + n0 + (e & 63)];
            }
        }

#pragma unroll
        for (int kk = 0; kk < 16; kk++) {
            float4 b4 = *(const float4*)&Bs[kk][tx * 4];
            float a[4];
#pragma unroll
            for (int i = 0; i < 4; i++) a[i] = As[ty * 4 + i][kk];
#pragma unroll
            for (int i = 0; i < 4; i++) {
                acc[i][0] += a[i] * b4.x;
                acc[i][1] += a[i] * b4.y;
                acc[i][2] += a[i] * b4.z;
                acc[i][3] += a[i] * b4.w;
            }
        }
        __syncthreads();
    }

    float* Pp = P + (size_t)blockIdx.y * 64 * N;
#pragma unroll
    for (int i = 0; i < 4; i++)
#pragma unroll
        for (int j = 0; j < 4; j++)
            Pp[(ty * 4 + i) * N + n0 + tx * 4 + j] = acc[i][j];
}

// reduce KSPLIT partials + bias
__global__ void reduceK(const float* __restrict__ P, const float* __restrict__ bias,
                        float* __restrict__ C, int N, int total)
{
    int i = blockIdx.x * blockDim.x + threadIdx.x;
    if (i < total) {
        float v = 0.f;
#pragma unroll
        for (int p = 0; p < KSPLIT; p++) v += P[(size_t)p * total + i];
        C[i] = v + bias[i % N];
    }
}

// ---------------------------------------------------------------------------
// Flash-decode partition kernel: block = (seq, head, partition), 256 threads
// Each partition handles up to PART_LEN tokens; writes partial (acc, m, l).
// ---------------------------------------------------------------------------
__global__ __launch_bounds__(256) void attn_part_kernel(
    const float* __restrict__ kv_cache,      // [2, NB, bs, h, d]
    const int* __restrict__ block_tables,    // [S, MAX_BLOCKS]
    const int* __restrict__ seq_lens,        // [S]
    const float* __restrict__ qbuf)          // [S, HIDDEN]
{
    const int s = blockIdx.x;
    const int h = blockIdx.y;
    const int p = blockIdx.z;
    const int tid = threadIdx.x;
    const int warp = tid >> 5;
    const int lane = tid & 31;

    const int L  = seq_lens[s];
    const int t0 = p * PART_LEN;
    const int Lp = min(L - t0, PART_LEN);    // may be <= 0

    const int pidx = (s * NUM_HEADS + h) * PART + p;
    float* pacc = g_pacc + (size_t)pidx * HEAD_DIM;

    if (Lp <= 0) {
        if (tid < HEAD_DIM) pacc[tid] = 0.f;
        if (tid == 0) g_pml[pidx] = make_float2(-INFINITY, 0.f);
        return;
    }

    __shared__ float q[HEAD_DIM];
    __shared__ float scores[PART_LEN];
    __shared__ float accbuf[8 * HEAD_DIM];
    __shared__ float red[8];

    if (tid < HEAD_DIM) q[tid] = qbuf[s * HIDDEN + h * HEAD_DIM + tid];
    __syncthreads();

    const float4 qv = *(const float4*)&q[lane * 4];
    const float* kc = kv_cache;
    const float* vc = kv_cache + (size_t)NUM_BLOCKS_KV * BLOCK_SIZE * NUM_HEADS * HEAD_DIM;
    const int* bt = block_tables + s * MAX_BLOCKS;

    // Pass 1: scores
    float lmax = -INFINITY;
#pragma unroll 4
    for (int t = warp; t < Lp; t += 8) {
        int gt = t0 + t;
        int blk = bt[gt >> 6];
        const float* kr = kc + (((size_t)blk * BLOCK_SIZE + (gt & 63)) * NUM_HEADS + h) * HEAD_DIM;
        float4 k4 = *(const float4*)(kr + lane * 4);
        float d = qv.x * k4.x + qv.y * k4.y + qv.z * k4.z + qv.w * k4.w;
#pragma unroll
        for (int o = 16; o; o >>= 1) d += __shfl_xor_sync(0xffffffffu, d, o);
        d *= SCALE;
        if (lane == 0) scores[t] = d;
        lmax = fmaxf(lmax, d);
    }
    if (lane == 0) red[warp] = lmax;
    __syncthreads();
    float gmax = red[0];
#pragma unroll
    for (int w = 1; w < 8; w++) gmax = fmaxf(gmax, red[w]);
    __syncthreads();

    // exp + sum (unnormalized)
    float lsum = 0.f;
    for (int t = tid; t < Lp; t += 256) {
        float e = __expf(scores[t] - gmax);
        scores[t] = e;
        lsum += e;
    }
#pragma unroll
    for (int o = 16; o; o >>= 1) lsum += __shfl_xor_sync(0xffffffffu, lsum, o);
    if (lane == 0) red[warp] = lsum;
    __syncthreads();

    // Pass 2: acc = sum_t w[t] * V[t]  (unnormalized)
    float4 acc = make_float4(0.f, 0.f, 0.f, 0.f);
#pragma unroll 4
    for (int t = warp; t < Lp; t += 8) {
        int gt = t0 + t;
        int blk = bt[gt >> 6];
        const float* vr = vc + (((size_t)blk * BLOCK_SIZE + (gt & 63)) * NUM_HEADS + h) * HEAD_DIM;
        float4 v4 = *(const float4*)(vr + lane * 4);
        float w = scores[t];
        acc.x += w * v4.x;
        acc.y += w * v4.y;
        acc.z += w * v4.z;
        acc.w += w * v4.w;
    }
    ((float4*)accbuf)[warp * 32 + lane] = acc;   // [warp][128 dims]
    __syncthreads();

    if (tid < HEAD_DIM) {
        float tot = 0.f;
#pragma unroll
        for (int w = 0; w < 8; w++) tot += accbuf[w * HEAD_DIM + tid];
        pacc[tid] = tot;
    }
    if (tid == 0) {
        float ls = 0.f;
#pragma unroll
        for (int w = 0; w < 8; w++) ls += red[w];
        g_pml[pidx] = make_float2(gmax, ls);
    }
}

// Combine partitions: block = (seq, head), 128 threads
__global__ __launch_bounds__(128) void attn_combine_kernel(float* __restrict__ out)
{
    const int s = blockIdx.x;
    const int h = blockIdx.y;
    const int d = threadIdx.x;
    const int base = (s * NUM_HEADS + h) * PART;

    float2 ml[PART];
#pragma unroll
    for (int p = 0; p < PART; p++) ml[p] = g_pml[base + p];

    float m = ml[0].x;
#pragma unroll
    for (int p = 1; p < PART; p++) m = fmaxf(m, ml[p].x);

    float l = 0.f, o = 0.f;
#pragma unroll
    for (int p = 0; p < PART; p++) {
        float sc = __expf(ml[p].x - m);     // -inf -> 0
        l += ml[p].y * sc;
        o += g_pacc[(size_t)(base + p) * HEAD_DIM + d] * sc;
    }
    out[s * HIDDEN + h * HEAD_DIM + d] = o / l;
}

// ---------------------------------------------------------------------------
extern "C" void kernel_launch(void* const* d_in, const int* in_sizes, int n_in,
                              void* d_out, int out_size)
{
    const float* hidden  = (const float*)d_in[0];
    const float* kvcache = (const float*)d_in[1];
    const float* W_attn  = (const float*)d_in[2];
    const float* b_attn  = (const float*)d_in[3];
    const float* W_proj  = (const float*)d_in[4];
    const float* b_proj  = (const float*)d_in[5];
    const int*   btab    = (const int*)d_in[6];
    const int*   slens   = (const int*)d_in[7];
    float* out = (float*)d_out;

    float *gq, *gattn, *gpart;
    cudaGetSymbolAddress((void**)&gq, g_q);
    cudaGetSymbolAddress((void**)&gattn, g_attn);
    cudaGetSymbolAddress((void**)&gpart, g_part);

    const int total = NUM_SEQS * HIDDEN;  // 131072

    // 1) Q projection only (first HIDDEN columns of W_attn), split-K=16
    gemm_splitk<<<dim3(HIDDEN / 64, KSPLIT), 256>>>(hidden, W_attn, gpart, HIDDEN, 3 * HIDDEN, HIDDEN);
    reduceK<<<(total + 255) / 256, 256>>>(gpart, b_attn, gq, HIDDEN, total);

    // 2) paged attention: flash-decode split + combine
    attn_part_kernel<<<dim3(NUM_SEQS, NUM_HEADS, PART), 256>>>(kvcache, btab, slens, gq);
    attn_combine_kernel<<<dim3(NUM_SEQS, NUM_HEADS), 128>>>(gattn);

    // 3) output projection, split-K=16
    gemm_splitk<<<dim3(HIDDEN / 64, KSPLIT), 256>>>(gattn, W_proj, gpart, HIDDEN, HIDDEN, HIDDEN);
    reduceK<<<(total + 255) / 256, 256>>>(gpart, b_proj, out, HIDDEN, total);
}

// round 3
// speedup vs baseline: 2.2434x; 1.0343x over previous
#include <cuda_runtime.h>
#include <math.h>

#define HIDDEN 2048
#define NUM_HEADS 16
#define HEAD_DIM 128
#define BLOCK_SIZE 64
#define NUM_SEQS 64
#define MAX_SEQ_LEN 2048
#define MAX_BLOCKS 32
#define NUM_BLOCKS_KV 2048
#define SCALE 0.08838834764831843f   // 1/sqrt(128)

#define KSPLIT 16
#define PART 8
#define PART_LEN 256   // MAX_SEQ_LEN / PART

// Scratch (device globals; no allocation allowed)
__device__ float g_q[NUM_SEQS * HIDDEN];                   // Q projection result
__device__ float g_attn[NUM_SEQS * HIDDEN];                // attention output
__device__ float g_part[KSPLIT * NUM_SEQS * HIDDEN];       // split-K partials
__device__ float g_pacc[NUM_SEQS * NUM_HEADS * PART * HEAD_DIM]; // attn partial accum
__device__ float2 g_pml[NUM_SEQS * NUM_HEADS * PART];      // attn partial (m, l)

__device__ __forceinline__ float4 ldcs4(const float* p) {
    return __ldcs((const float4*)p);
}

// ---------------------------------------------------------------------------
// Split-K GEMM: P[ks] = A[64 x K-slice] @ B[K x N (ldb)]  (n-tile 64 wide)
// block: 256 threads, tile 64x64, BK=16, thread tile 4x4, split-K=16 over grid.y
// ---------------------------------------------------------------------------
__global__ __launch_bounds__(256) void gemm_splitk(
    const float* __restrict__ A, const float* __restrict__ B,
    float* __restrict__ P, int K, int ldb, int N)
{
    const int KS = K / KSPLIT;              // 128
    const int k_base = blockIdx.y * KS;
    const int n0 = blockIdx.x * 64;

    __shared__ float As[64][17];            // padded: conflict-free reads
    __shared__ float Bs[16][64];

    const int tid = threadIdx.x;
    const int tx = tid & 15;   // N dir (x4)
    const int ty = tid >> 4;   // M dir (x4)

    // float4 tile loaders: A tile 64x16 = 1024 floats = 256 x float4
    const int a_row = tid >> 2;          // 0..63
    const int a_c4  = (tid & 3) * 4;     // 0,4,8,12
    const int b_row = tid >> 4;          // 0..15
    const int b_c4  = (tid & 15) * 4;    // 0..60

    float acc[4][4];
#pragma unroll
    for (int i = 0; i < 4; i++)
#pragma unroll
        for (int j = 0; j < 4; j++) acc[i][j] = 0.f;

    float4 ra = *(const float4*)&A[a_row * K + k_base + a_c4];
    float4 rb = *(const float4*)&B[(size_t)(k_base + b_row) * ldb + n0 + b_c4];

    for (int k0 = k_base; k0 < k_base + KS; k0 += 16) {
        As[a_row][a_c4 + 0] = ra.x;
        As[a_row][a_c4 + 1] = ra.y;
        As[a_row][a_c4 + 2] = ra.z;
        As[a_row][a_c4 + 3] = ra.w;
        *(float4*)&Bs[b_row][b_c4] = rb;
        __syncthreads();

        if (k0 + 16 < k_base + KS) {
            int kn = k0 + 16;
            ra = *(const float4*)&A[a_row * K + kn + a_c4];
            rb = *(const float4*)&B[(size_t)(kn + b_row) * ldb + n0 + b_c4];
        }

#pragma unroll
        for (int kk = 0; kk < 16; kk++) {
            float4 b4 = *(const float4*)&Bs[kk][tx * 4];
            float a[4];
#pragma unroll
            for (int i = 0; i < 4; i++) a[i] = As[ty * 4 + i][kk];
#pragma unroll
            for (int i = 0; i < 4; i++) {
                acc[i][0] += a[i] * b4.x;
                acc[i][1] += a[i] * b4.y;
                acc[i][2] += a[i] * b4.z;
                acc[i][3] += a[i] * b4.w;
            }
        }
        __syncthreads();
    }

    float* Pp = P + (size_t)blockIdx.y * 64 * N;
#pragma unroll
    for (int i = 0; i < 4; i++) {
        float4 v = make_float4(acc[i][0], acc[i][1], acc[i][2], acc[i][3]);
        *(float4*)&Pp[(ty * 4 + i) * N + n0 + tx * 4] = v;
    }
}

// reduce KSPLIT partials + bias
__global__ void reduceK(const float* __restrict__ P, const float* __restrict__ bias,
                        float* __restrict__ C, int N, int total)
{
    int i = blockIdx.x * blockDim.x + threadIdx.x;
    if (i < total) {
        float v = 0.f;
#pragma unroll
        for (int p = 0; p < KSPLIT; p++) v += P[(size_t)p * total + i];
        C[i] = v + bias[i % N];
    }
}

// ---------------------------------------------------------------------------
// Flash-decode partition kernel: block = (seq, head, partition), 256 threads
// Each partition handles up to PART_LEN tokens; writes partial (acc, m, l).
// ---------------------------------------------------------------------------
__global__ __launch_bounds__(256) void attn_part_kernel(
    const float* __restrict__ kv_cache,      // [2, NB, bs, h, d]
    const int* __restrict__ block_tables,    // [S, MAX_BLOCKS]
    const int* __restrict__ seq_lens,        // [S]
    const float* __restrict__ qbuf)          // [S, HIDDEN]
{
    const int s = blockIdx.x;
    const int h = blockIdx.y;
    const int p = blockIdx.z;
    const int tid = threadIdx.x;
    const int warp = tid >> 5;
    const int lane = tid & 31;

    const int L  = seq_lens[s];
    const int t0 = p * PART_LEN;
    const int Lp = min(L - t0, PART_LEN);    // may be <= 0

    const int pidx = (s * NUM_HEADS + h) * PART + p;
    float* pacc = g_pacc + (size_t)pidx * HEAD_DIM;

    if (Lp <= 0) {
        if (tid < HEAD_DIM) pacc[tid] = 0.f;
        if (tid == 0) g_pml[pidx] = make_float2(-INFINITY, 0.f);
        return;
    }

    __shared__ float q[HEAD_DIM];
    __shared__ float scores[PART_LEN];
    __shared__ float accbuf[8 * HEAD_DIM];
    __shared__ float red[8];
    __shared__ int   sbt[PART_LEN / BLOCK_SIZE];   // 4 block ids for this partition

    if (tid < HEAD_DIM) q[tid] = qbuf[s * HIDDEN + h * HEAD_DIM + tid];
    if (tid < PART_LEN / BLOCK_SIZE)
        sbt[tid] = block_tables[s * MAX_BLOCKS + (t0 >> 6) + tid];
    __syncthreads();

    const float4 qv = *(const float4*)&q[lane * 4];
    const float* kc = kv_cache;
    const float* vc = kv_cache + (size_t)NUM_BLOCKS_KV * BLOCK_SIZE * NUM_HEADS * HEAD_DIM;

    // Pass 1: scores (warp per token, stride 8 warps)
    float lmax = -INFINITY;
#pragma unroll 4
    for (int t = warp; t < Lp; t += 8) {
        int blk = sbt[t >> 6];
        const float* kr = kc + (((size_t)blk * BLOCK_SIZE + ((t0 + t) & 63)) * NUM_HEADS + h) * HEAD_DIM;
        float4 k4 = ldcs4(kr + lane * 4);
        float d = qv.x * k4.x + qv.y * k4.y + qv.z * k4.z + qv.w * k4.w;
#pragma unroll
        for (int o = 16; o; o >>= 1) d += __shfl_xor_sync(0xffffffffu, d, o);
        d *= SCALE;
        if (lane == 0) scores[t] = d;
        lmax = fmaxf(lmax, d);
    }
    if (lane == 0) red[warp] = lmax;
    __syncthreads();
    float gmax = red[0];
#pragma unroll
    for (int w = 1; w < 8; w++) gmax = fmaxf(gmax, red[w]);
    __syncthreads();

    // exp + sum (unnormalized)
    float lsum = 0.f;
    for (int t = tid; t < Lp; t += 256) {
        float e = __expf(scores[t] - gmax);
        scores[t] = e;
        lsum += e;
    }
#pragma unroll
    for (int o = 16; o; o >>= 1) lsum += __shfl_xor_sync(0xffffffffu, lsum, o);
    if (lane == 0) red[warp] = lsum;
    __syncthreads();

    // Pass 2: acc = sum_t w[t] * V[t]  (unnormalized)
    float4 acc = make_float4(0.f, 0.f, 0.f, 0.f);
#pragma unroll 4
    for (int t = warp; t < Lp; t += 8) {
        int blk = sbt[t >> 6];
        const float* vr = vc + (((size_t)blk * BLOCK_SIZE + ((t0 + t) & 63)) * NUM_HEADS + h) * HEAD_DIM;
        float4 v4 = ldcs4(vr + lane * 4);
        float w = scores[t];
        acc.x += w * v4.x;
        acc.y += w * v4.y;
        acc.z += w * v4.z;
        acc.w += w * v4.w;
    }
    ((float4*)accbuf)[warp * 32 + lane] = acc;   // [warp][128 dims]
    __syncthreads();

    if (tid < HEAD_DIM) {
        float tot = 0.f;
#pragma unroll
        for (int w = 0; w < 8; w++) tot += accbuf[w * HEAD_DIM + tid];
        pacc[tid] = tot;
    }
    if (tid == 0) {
        float ls = 0.f;
#pragma unroll
        for (int w = 0; w < 8; w++) ls += red[w];
        g_pml[pidx] = make_float2(gmax, ls);
    }
}

// Combine partitions: block = (seq, head), 128 threads
__global__ __launch_bounds__(128) void attn_combine_kernel(float* __restrict__ out)
{
    const int s = blockIdx.x;
    const int h = blockIdx.y;
    const int d = threadIdx.x;
    const int base = (s * NUM_HEADS + h) * PART;

    float2 ml[PART];
#pragma unroll
    for (int p = 0; p < PART; p++) ml[p] = g_pml[base + p];

    float m = ml[0].x;
#pragma unroll
    for (int p = 1; p < PART; p++) m = fmaxf(m, ml[p].x);

    float l = 0.f, o = 0.f;
#pragma unroll
    for (int p = 0; p < PART; p++) {
        float sc = __expf(ml[p].x - m);     // -inf -> 0
        l += ml[p].y * sc;
        o += g_pacc[(size_t)(base + p) * HEAD_DIM + d] * sc;
    }
    out[s * HIDDEN + h * HEAD_DIM + d] = o / l;
}

// ---------------------------------------------------------------------------
extern "C" void kernel_launch(void* const* d_in, const int* in_sizes, int n_in,
                              void* d_out, int out_size)
{
    const float* hidden  = (const float*)d_in[0];
    const float* kvcache = (const float*)d_in[1];
    const float* W_attn  = (const float*)d_in[2];
    const float* b_attn  = (const float*)d_in[3];
    const float* W_proj  = (const float*)d_in[4];
    const float* b_proj  = (const float*)d_in[5];
    const int*   btab    = (const int*)d_in[6];
    const int*   slens   = (const int*)d_in[7];
    float* out = (float*)d_out;

    float *gq, *gattn, *gpart;
    cudaGetSymbolAddress((void**)&gq, g_q);
    cudaGetSymbolAddress((void**)&gattn, g_attn);
    cudaGetSymbolAddress((void**)&gpart, g_part);

    const int total = NUM_SEQS * HIDDEN;  // 131072

    // 1) Q projection only (first HIDDEN columns of W_attn), split-K=16
    gemm_splitk<<<dim3(HIDDEN / 64, KSPLIT), 256>>>(hidden, W_attn, gpart, HIDDEN, 3 * HIDDEN, HIDDEN);
    reduceK<<<(total + 255) / 256, 256>>>(gpart, b_attn, gq, HIDDEN, total);

    // 2) paged attention: flash-decode split + combine
    attn_part_kernel<<<dim3(NUM_SEQS, NUM_HEADS, PART), 256>>>(kvcache, btab, slens, gq);
    attn_combine_kernel<<<dim3(NUM_SEQS, NUM_HEADS), 128>>>(gattn);

    // 3) output projection, split-K=16
    gemm_splitk<<<dim3(HIDDEN / 64, KSPLIT), 256>>>(gattn, W_proj, gpart, HIDDEN, HIDDEN, HIDDEN);
    reduceK<<<(total + 255) / 256, 256>>>(gpart, b_proj, out, HIDDEN, total);
}